// round 5
// baseline (speedup 1.0000x reference)
#include <cuda_runtime.h>
#include <cuda_bf16.h>
#include <math.h>

#define MAX_NI 50000
#define DD 32

// Scratch (allowed: __device__ globals, no runtime allocation)
__device__ float g_t_table[MAX_NI * DD];   // t[i][d] = sum_e W_bil[d][e]*item_e[i][e]
__device__ float g_c_table[MAX_NI * 8];    // c[i][j] = sum_e W1[j][64+e]*item_e[i][e]
__device__ int   g_mask_u8;                // 1 = mask stored as 1-byte elems, 0 = 4-byte

// ---------------------------------------------------------------------------
// Detect mask element width. mask[b][0] is always true (length >= 1) and
// lengths are uniform in [1,16], so the first 4KB contains many 1-values.
// A nonzero byte at offset%4==1 can only occur for 1-byte storage:
// int32(1) = {01,00,00,00} and float32(1.0f) = {00,00,80,3F} both have
// byte1 == 0.
// ---------------------------------------------------------------------------
__global__ void detect_mask_fmt_kernel(const unsigned char* __restrict__ mb) {
    __shared__ int s;
    if (threadIdx.x == 0) s = 0;
    __syncthreads();
    int l = 0;
    for (int k = threadIdx.x * 4 + 1; k < 4096; k += blockDim.x * 4)
        if (mb[k] != 0) l = 1;
    if (l) atomicOr(&s, 1);
    __syncthreads();
    if (threadIdx.x == 0) g_mask_u8 = s;
}

// ---------------------------------------------------------------------------
// Per-item precompute: t = W_bil @ item_e  and  c = W1[:, 64:96] @ item_e.
// One warp per item, lane = dim.
// ---------------------------------------------------------------------------
__global__ void precompute_kernel(const float* __restrict__ item_table,
                                  const float* __restrict__ W_bil,
                                  const float* __restrict__ W1,
                                  int NI) {
    __shared__ float Wt[32 * 32];    // Wt[e*32+d] = W_bil[d*32+e] (transposed)
    __shared__ float W1c[8 * 33];    // padded against bank conflicts
    int tid = threadIdx.x;           // 128 threads
    for (int k = tid; k < 1024; k += 128) {
        int d = k >> 5, e = k & 31;
        Wt[e * 32 + d] = W_bil[k];
    }
    for (int k = tid; k < 256; k += 128) {
        int j = k >> 5, e = k & 31;
        W1c[j * 33 + e] = W1[j * 96 + 64 + e];
    }
    __syncthreads();

    int warp = tid >> 5, lane = tid & 31;
    int i = blockIdx.x * 4 + warp;
    if (i >= NI) return;

    float itemv = item_table[i * 32 + lane];
    float t = 0.f, c = 0.f;
#pragma unroll
    for (int e = 0; e < 32; e++) {
        float bc = __shfl_sync(0xffffffffu, itemv, e);
        t = fmaf(Wt[e * 32 + lane], bc, t);
        if (lane < 8) c = fmaf(W1c[lane * 33 + e], bc, c);
    }
    g_t_table[i * 32 + lane] = t;
    if (lane < 8) g_c_table[i * 8 + lane] = c;
}

__device__ __forceinline__ unsigned bytes_to_bits4(unsigned w) {
    return (unsigned)(((w & 0xFFu) != 0) | ((((w >> 8) & 0xFFu) != 0) << 1) |
                      ((((w >> 16) & 0xFFu) != 0) << 2) | (((w >> 24) != 0) << 3));
}

// ---------------------------------------------------------------------------
// Main kernel: 8 lanes per pair, float4 per lane (d in [4q, 4q+4)).
// Block = 256 threads = 32 pairs. Index/mask rows are loaded as int4 by
// lanes 0-3 (ids) / 4-7 (mask) and distributed via SHFL; mask is compressed
// to a 16-bit validity word. Member gathers are issued in explicit batches
// of 8 back-to-back predicated LDG.128s (MLP_p1 = 8) before any dependent
// SHFL-reduction consumes them. launch_bounds(256,2) guarantees >=16
// warps/SM even if the register batch pushes natural usage past 128.
// ---------------------------------------------------------------------------
__global__ void __launch_bounds__(256, 2)
bilinear_main_kernel(const int*  __restrict__ item_inputs,
                     const int*  __restrict__ member_ids,
                     const void* __restrict__ mask_raw,
                     const float* __restrict__ user_table,
                     const float* __restrict__ item_table,
                     const float* __restrict__ b_bil,
                     const float* __restrict__ W1,
                     const float* __restrict__ b1,
                     const float* __restrict__ W2,
                     const float* __restrict__ b2,
                     float* __restrict__ out,
                     int B) {
    __shared__ float W1s[8 * 64];   // first 64 cols of each W1 row (x0 | x1 parts)
    __shared__ float W2s[8];
    __shared__ float b1s[8];
    int tid = threadIdx.x;
    for (int k = tid; k < 512; k += 256) {
        int j = k >> 6, d = k & 63;
        W1s[k] = W1[j * 96 + d];
    }
    if (tid < 8) { W2s[tid] = W2[tid]; b1s[tid] = b1[tid]; }
    __syncthreads();

    int lane = tid & 31;
    int q    = lane & 7;
    int base = lane & ~7;            // first lane of this pair's 8-lane group
    int p = blockIdx.x * 32 + (tid >> 3);
    if (p >= B) p = B - 1;           // keep all 32 lanes alive for shfl_sync

    int item = item_inputs[p];
    float4 itm = ((const float4*)(item_table + item * 32))[q];
    float4 t4  = ((const float4*)(g_t_table  + item * 32))[q];
    float  cq  = g_c_table[item * 8 + q];
    float  bb  = b_bil[0];
    bool   u8  = (g_mask_u8 != 0);

    // Cooperative row load: lanes 0-3 ids, lanes 4-7 mask.
    int4 va = make_int4(0, 0, 0, 0);
    if (q < 4) {
        va = ((const int4*)member_ids)[p * 4 + q];
    } else if (!u8) {
        va = ((const int4*)mask_raw)[p * 4 + (q - 4)];
    } else if (q == 4) {
        va = ((const int4*)mask_raw)[p];
    }

    // Lanes 4-7 build position-shifted validity bits; OR-combine via 4 SHFLs.
    unsigned part = 0;
    if (q >= 4) {
        if (!u8) {
            unsigned nib = (unsigned)((va.x != 0) | ((va.y != 0) << 1) |
                                      ((va.z != 0) << 2) | ((va.w != 0) << 3));
            part = nib << ((q - 4) * 4);
        } else if (q == 4) {
            part = bytes_to_bits4((unsigned)va.x)
                 | (bytes_to_bits4((unsigned)va.y) << 4)
                 | (bytes_to_bits4((unsigned)va.z) << 8)
                 | (bytes_to_bits4((unsigned)va.w) << 12);
        }
    }
    unsigned m16 = __shfl_sync(0xffffffffu, part, base + 4)
                 | __shfl_sync(0xffffffffu, part, base + 5)
                 | __shfl_sync(0xffffffffu, part, base + 6)
                 | __shfl_sync(0xffffffffu, part, base + 7);

    float4 fu = make_float4(0.f, 0.f, 0.f, 0.f);
#pragma unroll
    for (int half = 0; half < 2; half++) {
        // Phase 1: 8 back-to-back predicated gathers into a register batch.
        float4 me[8];
#pragma unroll
        for (int j = 0; j < 8; j++) {
            int m = half * 8 + j;
            int idreg = ((m & 3) == 0) ? va.x : ((m & 3) == 1) ? va.y
                      : ((m & 3) == 2) ? va.z : va.w;
            int mid = __shfl_sync(0xffffffffu, idreg, base + (m >> 2));
            bool valid = (m16 >> m) & 1u;
            me[j] = make_float4(0.f, 0.f, 0.f, 0.f);
            if (valid)
                me[j] = __ldg((const float4*)(user_table + (size_t)mid * 32) + q);
        }
        // Phase 2: 8 independent score reductions (SHFL chains pipeline).
#pragma unroll
        for (int j = 0; j < 8; j++) {
            int m = half * 8 + j;
            float pd = fmaf(me[j].x, t4.x, fmaf(me[j].y, t4.y,
                       fmaf(me[j].z, t4.z, me[j].w * t4.w)));
            pd += __shfl_xor_sync(0xffffffffu, pd, 1);
            pd += __shfl_xor_sync(0xffffffffu, pd, 2);
            pd += __shfl_xor_sync(0xffffffffu, pd, 4);
            bool valid = (m16 >> m) & 1u;
            float w = valid ? (pd + bb) : 0.f;
            fu.x = fmaf(w, me[j].x, fu.x); fu.y = fmaf(w, me[j].y, fu.y);
            fu.z = fmaf(w, me[j].z, fu.z); fu.w = fmaf(w, me[j].w, fu.w);
        }
    }

    // MLP: h = relu(W1 @ [fu*item, fu, item] + b1); item part precomputed (cq).
    float4 x0 = make_float4(fu.x * itm.x, fu.y * itm.y, fu.z * itm.z, fu.w * itm.w);
    float h[8];
#pragma unroll
    for (int j = 0; j < 8; j++) {
        float4 a  = *(const float4*)(W1s + j * 64 + 4 * q);
        float4 bq = *(const float4*)(W1s + j * 64 + 32 + 4 * q);
        float pp = fmaf(a.x, x0.x, fmaf(a.y, x0.y, fmaf(a.z, x0.z, a.w * x0.w)))
                 + fmaf(bq.x, fu.x, fmaf(bq.y, fu.y, fmaf(bq.z, fu.z, bq.w * fu.w)));
        if (j == q) pp += cq + b1s[q];   // fold item-MLP part + bias exactly once
        pp += __shfl_xor_sync(0xffffffffu, pp, 1);
        pp += __shfl_xor_sync(0xffffffffu, pp, 2);
        pp += __shfl_xor_sync(0xffffffffu, pp, 4);
        h[j] = pp;
    }

    if (q == 0) {
        float acc = b2[0];
#pragma unroll
        for (int j = 0; j < 8; j++) acc = fmaf(W2s[j], fmaxf(h[j], 0.f), acc);
        out[p] = 1.f / (1.f + __expf(-acc));
    }
}

extern "C" void kernel_launch(void* const* d_in, const int* in_sizes, int n_in,
                              void* d_out, int out_size) {
    const int*   item_inputs = (const int*)  d_in[0];
    const int*   member_ids  = (const int*)  d_in[1];
    const void*  member_mask =               d_in[2];
    const float* user_table  = (const float*)d_in[3];
    const float* item_table  = (const float*)d_in[4];
    const float* W_bil       = (const float*)d_in[5];
    const float* b_bil       = (const float*)d_in[6];
    const float* W1          = (const float*)d_in[7];
    const float* b1          = (const float*)d_in[8];
    const float* W2          = (const float*)d_in[9];
    const float* b2          = (const float*)d_in[10];
    float* out = (float*)d_out;

    int B  = in_sizes[0];
    int NI = in_sizes[4] / 32;

    detect_mask_fmt_kernel<<<1, 128>>>((const unsigned char*)member_mask);
    precompute_kernel<<<(NI + 3) / 4, 128>>>(item_table, W_bil, W1, NI);
    bilinear_main_kernel<<<(B + 31) / 32, 256>>>(
        item_inputs, member_ids, member_mask, user_table, item_table,
        b_bil, W1, b1, W2, b2, out, B);
}

// round 11
// speedup vs baseline: 1.4234x; 1.4234x over previous
#include <cuda_runtime.h>
#include <cuda_bf16.h>
#include <math.h>

#define MAX_NI 50000
#define DD 32

// Scratch (allowed: __device__ globals, no runtime allocation)
__device__ float g_t_table[MAX_NI * DD];   // t[i][d] = sum_e W_bil[d][e]*item_e[i][e]
__device__ float g_c_table[MAX_NI * 8];    // c[i][j] = sum_e W1[j][64+e]*item_e[i][e]
__device__ int   g_mask_u8;                // 1 = mask stored as 1-byte elems, 0 = 4-byte

// ---------------------------------------------------------------------------
// Precompute kernel (grid-stride, 2 blocks/SM) with mask-format detection
// folded into block 0. Detection: mask[b][0] is always true (length >= 1) and
// lengths are uniform in [1,16], so the first 4KB contains many 1-values. A
// nonzero byte at offset%4==1 can only occur for 1-byte storage:
// int32(1) = {01,00,00,00}, float32(1.0f) = {00,00,80,3F} both have byte1==0.
// ---------------------------------------------------------------------------
__global__ void __launch_bounds__(256)
precompute_kernel(const float* __restrict__ item_table,
                  const float* __restrict__ W_bil,
                  const float* __restrict__ W1,
                  const unsigned char* __restrict__ mask_bytes,
                  int NI) {
    __shared__ float Wt[32 * 32];    // Wt[e*32+d] = W_bil[d*32+e] (transposed)
    __shared__ float W1c[8 * 33];    // padded against bank conflicts
    __shared__ int s_u8;
    int tid = threadIdx.x;           // 256 threads

    // Block 0: detect mask element width over first 4KB (uniform branch).
    if (blockIdx.x == 0) {
        if (tid == 0) s_u8 = 0;
        __syncthreads();
        int l = 0;
        for (int k = tid * 4 + 1; k < 4096; k += blockDim.x * 4)
            if (mask_bytes[k] != 0) l = 1;
        if (l) atomicOr(&s_u8, 1);
        __syncthreads();
        if (tid == 0) g_mask_u8 = s_u8;
    }

    // Stage weights once per block.
    for (int k = tid; k < 1024; k += 256) {
        int d = k >> 5, e = k & 31;
        Wt[e * 32 + d] = W_bil[k];
    }
    if (tid < 256) {
        int j = tid >> 5, e = tid & 31;
        if (j < 8) W1c[j * 33 + e] = W1[j * 96 + 64 + e];
    }
    __syncthreads();

    // Grid-stride over items, one warp per item.
    int lane = tid & 31;
    int gw   = blockIdx.x * 8 + (tid >> 5);
    int nw   = gridDim.x * 8;
    for (int i = gw; i < NI; i += nw) {
        float itemv = item_table[i * 32 + lane];
        float t = 0.f, c = 0.f;
#pragma unroll
        for (int e = 0; e < 32; e++) {
            float bc = __shfl_sync(0xffffffffu, itemv, e);
            t = fmaf(Wt[e * 32 + lane], bc, t);
            if (lane < 8) c = fmaf(W1c[lane * 33 + e], bc, c);
        }
        g_t_table[i * 32 + lane] = t;
        if (lane < 8) g_c_table[i * 8 + lane] = c;
    }
}

__device__ __forceinline__ unsigned bytes_to_bits4(unsigned w) {
    return (unsigned)(((w & 0xFFu) != 0) | ((((w >> 8) & 0xFFu) != 0) << 1) |
                      ((((w >> 16) & 0xFFu) != 0) << 2) | (((w >> 24) != 0) << 3));
}

// ---------------------------------------------------------------------------
// Main kernel: 8 lanes per pair, float4 per lane (d in [4q, 4q+4)).
// Block = 256 threads = 32 pairs. Index/mask rows are loaded as int4 by
// lanes 0-3 (ids) / 4-7 (mask) and distributed via SHFL; mask is compressed
// to a 16-bit validity word. Member gathers run in four batches of 4
// back-to-back predicated LDG.128s (MLP_p1 = 4) -- batch shrunk from 8 to
// keep peak live registers safely under the launch_bounds(256,2) cap of 128
// and avoid STL/LDL spills in the hot loop.
// ---------------------------------------------------------------------------
__global__ void __launch_bounds__(256, 2)
bilinear_main_kernel(const int*  __restrict__ item_inputs,
                     const int*  __restrict__ member_ids,
                     const void* __restrict__ mask_raw,
                     const float* __restrict__ user_table,
                     const float* __restrict__ item_table,
                     const float* __restrict__ b_bil,
                     const float* __restrict__ W1,
                     const float* __restrict__ b1,
                     const float* __restrict__ W2,
                     const float* __restrict__ b2,
                     float* __restrict__ out,
                     int B) {
    __shared__ float W1s[8 * 64];   // first 64 cols of each W1 row (x0 | x1 parts)
    __shared__ float W2s[8];
    __shared__ float b1s[8];
    int tid = threadIdx.x;
    for (int k = tid; k < 512; k += 256) {
        int j = k >> 6, d = k & 63;
        W1s[k] = W1[j * 96 + d];
    }
    if (tid < 8) { W2s[tid] = W2[tid]; b1s[tid] = b1[tid]; }
    __syncthreads();

    int lane = tid & 31;
    int q    = lane & 7;
    int base = lane & ~7;            // first lane of this pair's 8-lane group
    int p = blockIdx.x * 32 + (tid >> 3);
    if (p >= B) p = B - 1;           // keep all 32 lanes alive for shfl_sync

    int item = item_inputs[p];
    float4 itm = ((const float4*)(item_table + item * 32))[q];
    float4 t4  = ((const float4*)(g_t_table  + item * 32))[q];
    float  cq  = g_c_table[item * 8 + q];
    float  bb  = b_bil[0];
    bool   u8  = (g_mask_u8 != 0);

    // Cooperative row load: lanes 0-3 ids, lanes 4-7 mask.
    int4 va = make_int4(0, 0, 0, 0);
    if (q < 4) {
        va = ((const int4*)member_ids)[p * 4 + q];
    } else if (!u8) {
        va = ((const int4*)mask_raw)[p * 4 + (q - 4)];
    } else if (q == 4) {
        va = ((const int4*)mask_raw)[p];
    }

    // Lanes 4-7 build position-shifted validity bits; OR-combine via 4 SHFLs.
    unsigned part = 0;
    if (q >= 4) {
        if (!u8) {
            unsigned nib = (unsigned)((va.x != 0) | ((va.y != 0) << 1) |
                                      ((va.z != 0) << 2) | ((va.w != 0) << 3));
            part = nib << ((q - 4) * 4);
        } else if (q == 4) {
            part = bytes_to_bits4((unsigned)va.x)
                 | (bytes_to_bits4((unsigned)va.y) << 4)
                 | (bytes_to_bits4((unsigned)va.z) << 8)
                 | (bytes_to_bits4((unsigned)va.w) << 12);
        }
    }
    unsigned m16 = __shfl_sync(0xffffffffu, part, base + 4)
                 | __shfl_sync(0xffffffffu, part, base + 5)
                 | __shfl_sync(0xffffffffu, part, base + 6)
                 | __shfl_sync(0xffffffffu, part, base + 7);

    float4 fu = make_float4(0.f, 0.f, 0.f, 0.f);
#pragma unroll
    for (int quarter = 0; quarter < 4; quarter++) {
        // Phase 1: 4 back-to-back predicated gathers into a register batch.
        // All 4 ids of this quarter live in lane base+quarter, components x..w.
        float4 me[4];
#pragma unroll
        for (int j = 0; j < 4; j++) {
            int idreg = (j == 0) ? va.x : (j == 1) ? va.y : (j == 2) ? va.z : va.w;
            int mid = __shfl_sync(0xffffffffu, idreg, base + quarter);
            bool valid = (m16 >> (quarter * 4 + j)) & 1u;
            me[j] = make_float4(0.f, 0.f, 0.f, 0.f);
            if (valid)
                me[j] = __ldg((const float4*)(user_table + (size_t)mid * 32) + q);
        }
        // Phase 2: 4 independent score reductions (SHFL chains pipeline).
#pragma unroll
        for (int j = 0; j < 4; j++) {
            float pd = fmaf(me[j].x, t4.x, fmaf(me[j].y, t4.y,
                       fmaf(me[j].z, t4.z, me[j].w * t4.w)));
            pd += __shfl_xor_sync(0xffffffffu, pd, 1);
            pd += __shfl_xor_sync(0xffffffffu, pd, 2);
            pd += __shfl_xor_sync(0xffffffffu, pd, 4);
            bool valid = (m16 >> (quarter * 4 + j)) & 1u;
            float w = valid ? (pd + bb) : 0.f;
            fu.x = fmaf(w, me[j].x, fu.x); fu.y = fmaf(w, me[j].y, fu.y);
            fu.z = fmaf(w, me[j].z, fu.z); fu.w = fmaf(w, me[j].w, fu.w);
        }
    }

    // MLP: h = relu(W1 @ [fu*item, fu, item] + b1); item part precomputed (cq).
    float4 x0 = make_float4(fu.x * itm.x, fu.y * itm.y, fu.z * itm.z, fu.w * itm.w);
    float h[8];
#pragma unroll
    for (int j = 0; j < 8; j++) {
        float4 a  = *(const float4*)(W1s + j * 64 + 4 * q);
        float4 bq = *(const float4*)(W1s + j * 64 + 32 + 4 * q);
        float pp = fmaf(a.x, x0.x, fmaf(a.y, x0.y, fmaf(a.z, x0.z, a.w * x0.w)))
                 + fmaf(bq.x, fu.x, fmaf(bq.y, fu.y, fmaf(bq.z, fu.z, bq.w * fu.w)));
        if (j == q) pp += cq + b1s[q];   // fold item-MLP part + bias exactly once
        pp += __shfl_xor_sync(0xffffffffu, pp, 1);
        pp += __shfl_xor_sync(0xffffffffu, pp, 2);
        pp += __shfl_xor_sync(0xffffffffu, pp, 4);
        h[j] = pp;
    }

    if (q == 0) {
        float acc = b2[0];
#pragma unroll
        for (int j = 0; j < 8; j++) acc = fmaf(W2s[j], fmaxf(h[j], 0.f), acc);
        out[p] = 1.f / (1.f + __expf(-acc));
    }
}

extern "C" void kernel_launch(void* const* d_in, const int* in_sizes, int n_in,
                              void* d_out, int out_size) {
    const int*   item_inputs = (const int*)  d_in[0];
    const int*   member_ids  = (const int*)  d_in[1];
    const void*  member_mask =               d_in[2];
    const float* user_table  = (const float*)d_in[3];
    const float* item_table  = (const float*)d_in[4];
    const float* W_bil       = (const float*)d_in[5];
    const float* b_bil       = (const float*)d_in[6];
    const float* W1          = (const float*)d_in[7];
    const float* b1          = (const float*)d_in[8];
    const float* W2          = (const float*)d_in[9];
    const float* b2          = (const float*)d_in[10];
    float* out = (float*)d_out;

    int B  = in_sizes[0];
    int NI = in_sizes[4] / 32;

    // 2 launches/call: precompute(+detect) then main. With the harness ncu
    // capture at launch index 5, the captured kernel is the main one.
    precompute_kernel<<<296, 256>>>(item_table, W_bil, W1,
                                    (const unsigned char*)member_mask, NI);
    bilinear_main_kernel<<<(B + 31) / 32, 256>>>(
        item_inputs, member_ids, member_mask, user_table, item_table,
        b_bil, W1, b1, W2, b2, out, B);
}

// round 13
// speedup vs baseline: 1.6860x; 1.1845x over previous
#include <cuda_runtime.h>
#include <cuda_bf16.h>
#include <math.h>

#define MAX_NI 50000
#define DD 32

// Scratch (allowed: __device__ globals, no runtime allocation)
__device__ float g_t_table[MAX_NI * DD];   // t[i][d] = sum_e W_bil[d][e]*item_e[i][e]
__device__ float g_c_table[MAX_NI * 8];    // c[i][j] = sum_e W1[j][64+e]*item_e[i][e]
__device__ int   g_mask_u8;                // 1 = mask stored as 1-byte elems, 0 = 4-byte

// ---------------------------------------------------------------------------
// Precompute kernel (grid-stride, 2 blocks/SM) with mask-format detection
// folded into block 0. Detection: mask[b][0] is always true (length >= 1) and
// lengths are uniform in [1,16], so the first 4KB contains many 1-values. A
// nonzero byte at offset%4==1 can only occur for 1-byte storage:
// int32(1) = {01,00,00,00}, float32(1.0f) = {00,00,80,3F} both have byte1==0.
// ---------------------------------------------------------------------------
__global__ void __launch_bounds__(256)
precompute_kernel(const float* __restrict__ item_table,
                  const float* __restrict__ W_bil,
                  const float* __restrict__ W1,
                  const unsigned char* __restrict__ mask_bytes,
                  int NI) {
    __shared__ float Wt[32 * 32];    // Wt[e*32+d] = W_bil[d*32+e] (transposed)
    __shared__ float W1c[8 * 33];    // padded against bank conflicts
    __shared__ int s_u8;
    int tid = threadIdx.x;           // 256 threads

    // Block 0: detect mask element width over first 4KB (uniform branch).
    if (blockIdx.x == 0) {
        if (tid == 0) s_u8 = 0;
        __syncthreads();
        int l = 0;
        for (int k = tid * 4 + 1; k < 4096; k += blockDim.x * 4)
            if (mask_bytes[k] != 0) l = 1;
        if (l) atomicOr(&s_u8, 1);
        __syncthreads();
        if (tid == 0) g_mask_u8 = s_u8;
    }

    // Stage weights once per block.
    for (int k = tid; k < 1024; k += 256) {
        int d = k >> 5, e = k & 31;
        Wt[e * 32 + d] = W_bil[k];
    }
    if (tid < 256) {
        int j = tid >> 5, e = tid & 31;
        if (j < 8) W1c[j * 33 + e] = W1[j * 96 + 64 + e];
    }
    __syncthreads();

    // Grid-stride over items, one warp per item.
    int lane = tid & 31;
    int gw   = blockIdx.x * 8 + (tid >> 5);
    int nw   = gridDim.x * 8;
    for (int i = gw; i < NI; i += nw) {
        float itemv = item_table[i * 32 + lane];
        float t = 0.f, c = 0.f;
#pragma unroll
        for (int e = 0; e < 32; e++) {
            float bc = __shfl_sync(0xffffffffu, itemv, e);
            t = fmaf(Wt[e * 32 + lane], bc, t);
            if (lane < 8) c = fmaf(W1c[lane * 33 + e], bc, c);
        }
        g_t_table[i * 32 + lane] = t;
        if (lane < 8) g_c_table[i * 8 + lane] = c;
    }
}

__device__ __forceinline__ unsigned bytes_to_bits4(unsigned w) {
    return (unsigned)(((w & 0xFFu) != 0) | ((((w >> 8) & 0xFFu) != 0) << 1) |
                      ((((w >> 16) & 0xFFu) != 0) << 2) | (((w >> 24) != 0) << 3));
}

// ---------------------------------------------------------------------------
// Main kernel: 8 lanes per pair, float4 per lane (d in [4q, 4q+4)).
// Block = 256 threads = 32 pairs. R11 profile showed occ=22.9% (16 warps, 118
// regs under launch_bounds(256,2)) with nothing saturated (L1 46%, issue 37%)
// => latency-bound via occupancy. This version targets 64 regs / 32 warps:
//   - h[8] eliminated (W2 dot fused into the reduction loop)
//   - itm/cq loads moved after the gather loop (shorter live ranges)
//   - launch_bounds(256, 4)
// ---------------------------------------------------------------------------
__global__ void __launch_bounds__(256, 4)
bilinear_main_kernel(const int*  __restrict__ item_inputs,
                     const int*  __restrict__ member_ids,
                     const void* __restrict__ mask_raw,
                     const float* __restrict__ user_table,
                     const float* __restrict__ item_table,
                     const float* __restrict__ b_bil,
                     const float* __restrict__ W1,
                     const float* __restrict__ b1,
                     const float* __restrict__ W2,
                     const float* __restrict__ b2,
                     float* __restrict__ out,
                     int B) {
    __shared__ float W1s[8 * 64];   // first 64 cols of each W1 row (x0 | x1 parts)
    __shared__ float W2s[8];
    __shared__ float b1s[8];
    int tid = threadIdx.x;
    for (int k = tid; k < 512; k += 256) {
        int j = k >> 6, d = k & 63;
        W1s[k] = W1[j * 96 + d];
    }
    if (tid < 8) { W2s[tid] = W2[tid]; b1s[tid] = b1[tid]; }
    __syncthreads();

    int lane = tid & 31;
    int q    = lane & 7;
    int base = lane & ~7;            // first lane of this pair's 8-lane group
    int p = blockIdx.x * 32 + (tid >> 3);
    if (p >= B) p = B - 1;           // keep all 32 lanes alive for shfl_sync

    int item = item_inputs[p];
    float4 t4 = ((const float4*)(g_t_table + item * 32))[q];
    float  bb = b_bil[0];
    bool   u8 = (g_mask_u8 != 0);

    // Cooperative row load: lanes 0-3 ids, lanes 4-7 mask.
    int4 va = make_int4(0, 0, 0, 0);
    if (q < 4) {
        va = ((const int4*)member_ids)[p * 4 + q];
    } else if (!u8) {
        va = ((const int4*)mask_raw)[p * 4 + (q - 4)];
    } else if (q == 4) {
        va = ((const int4*)mask_raw)[p];
    }

    // Lanes 4-7 build position-shifted validity bits; OR-combine via 4 SHFLs.
    unsigned part = 0;
    if (q >= 4) {
        if (!u8) {
            unsigned nib = (unsigned)((va.x != 0) | ((va.y != 0) << 1) |
                                      ((va.z != 0) << 2) | ((va.w != 0) << 3));
            part = nib << ((q - 4) * 4);
        } else if (q == 4) {
            part = bytes_to_bits4((unsigned)va.x)
                 | (bytes_to_bits4((unsigned)va.y) << 4)
                 | (bytes_to_bits4((unsigned)va.z) << 8)
                 | (bytes_to_bits4((unsigned)va.w) << 12);
        }
    }
    unsigned m16 = __shfl_sync(0xffffffffu, part, base + 4)
                 | __shfl_sync(0xffffffffu, part, base + 5)
                 | __shfl_sync(0xffffffffu, part, base + 6)
                 | __shfl_sync(0xffffffffu, part, base + 7);

    float4 fu = make_float4(0.f, 0.f, 0.f, 0.f);
#pragma unroll
    for (int quarter = 0; quarter < 4; quarter++) {
        // Phase 1: 4 back-to-back predicated gathers into a register batch.
        // All 4 ids of this quarter live in lane base+quarter, components x..w.
        float4 me[4];
#pragma unroll
        for (int j = 0; j < 4; j++) {
            int idreg = (j == 0) ? va.x : (j == 1) ? va.y : (j == 2) ? va.z : va.w;
            int mid = __shfl_sync(0xffffffffu, idreg, base + quarter);
            bool valid = (m16 >> (quarter * 4 + j)) & 1u;
            me[j] = make_float4(0.f, 0.f, 0.f, 0.f);
            if (valid)
                me[j] = __ldg((const float4*)(user_table + (size_t)mid * 32) + q);
        }
        // Phase 2: 4 independent score reductions (SHFL chains pipeline).
#pragma unroll
        for (int j = 0; j < 4; j++) {
            float pd = fmaf(me[j].x, t4.x, fmaf(me[j].y, t4.y,
                       fmaf(me[j].z, t4.z, me[j].w * t4.w)));
            pd += __shfl_xor_sync(0xffffffffu, pd, 1);
            pd += __shfl_xor_sync(0xffffffffu, pd, 2);
            pd += __shfl_xor_sync(0xffffffffu, pd, 4);
            bool valid = (m16 >> (quarter * 4 + j)) & 1u;
            float w = valid ? (pd + bb) : 0.f;
            fu.x = fmaf(w, me[j].x, fu.x); fu.y = fmaf(w, me[j].y, fu.y);
            fu.z = fmaf(w, me[j].z, fu.z); fu.w = fmaf(w, me[j].w, fu.w);
        }
    }

    // MLP: h_j = relu(W1 @ [fu*item, fu, item] + b1)_j; item part precomputed
    // (cq). W2 dot fused into the loop -- no h[] array. itm/cq loaded only now
    // to keep hot-loop register pressure low.
    float4 itm = ((const float4*)(item_table + item * 32))[q];
    float  cq  = g_c_table[item * 8 + q];
    float4 x0 = make_float4(fu.x * itm.x, fu.y * itm.y, fu.z * itm.z, fu.w * itm.w);
    float acc = b2[0];
#pragma unroll
    for (int j = 0; j < 8; j++) {
        float4 a  = *(const float4*)(W1s + j * 64 + 4 * q);
        float4 bq = *(const float4*)(W1s + j * 64 + 32 + 4 * q);
        float pp = fmaf(a.x, x0.x, fmaf(a.y, x0.y, fmaf(a.z, x0.z, a.w * x0.w)))
                 + fmaf(bq.x, fu.x, fmaf(bq.y, fu.y, fmaf(bq.z, fu.z, bq.w * fu.w)));
        if (j == q) pp += cq + b1s[q];   // fold item-MLP part + bias exactly once
        pp += __shfl_xor_sync(0xffffffffu, pp, 1);
        pp += __shfl_xor_sync(0xffffffffu, pp, 2);
        pp += __shfl_xor_sync(0xffffffffu, pp, 4);
        acc = fmaf(W2s[j], fmaxf(pp, 0.f), acc);
    }

    if (q == 0) out[p] = 1.f / (1.f + __expf(-acc));
}

extern "C" void kernel_launch(void* const* d_in, const int* in_sizes, int n_in,
                              void* d_out, int out_size) {
    const int*   item_inputs = (const int*)  d_in[0];
    const int*   member_ids  = (const int*)  d_in[1];
    const void*  member_mask =               d_in[2];
    const float* user_table  = (const float*)d_in[3];
    const float* item_table  = (const float*)d_in[4];
    const float* W_bil       = (const float*)d_in[5];
    const float* b_bil       = (const float*)d_in[6];
    const float* W1          = (const float*)d_in[7];
    const float* b1          = (const float*)d_in[8];
    const float* W2          = (const float*)d_in[9];
    const float* b2          = (const float*)d_in[10];
    float* out = (float*)d_out;

    int B  = in_sizes[0];
    int NI = in_sizes[4] / 32;

    // 2 launches/call: precompute(+detect) then main. With the harness ncu
    // capture at launch index 5, the captured kernel is the main one.
    precompute_kernel<<<296, 256>>>(item_table, W_bil, W1,
                                    (const unsigned char*)member_mask, NI);
    bilinear_main_kernel<<<(B + 31) / 32, 256>>>(
        item_inputs, member_ids, member_mask, user_table, item_table,
        b_bil, W1, b1, W2, b2, out, B);
}